// round 2
// baseline (speedup 1.0000x reference)
#include <cuda_runtime.h>
#include <cstdint>

// Problem constants
#define NB 2
#define NC 128
#define HF 256
#define WF 256
#define NPF (HF*WF)          // 65536 pixels full res
#define HHALF 128
#define WHALF 128
#define NPH (HHALF*WHALF)    // 16384 pixels half res
#define NHEAD 8
#define CPH 16               // channels per head

// ---------------- scratch (static device globals; no allocations) ----------------
__device__ float g_qkv [(size_t)NB*3*NC*NPF];   // 50.3M elems
__device__ float g_qbuf[(size_t)NB*NC*NPF];     // reconstructed q (after IDWT)
__device__ float g_kbuf[(size_t)NB*NC*NPF];
__device__ float g_vbuf[(size_t)NB*NC*NPF];
__device__ float g_ll  [(size_t)NB*NC*NPH];
__device__ float g_lhb [(size_t)NB*NC*NPH];
__device__ float g_hlb [(size_t)NB*NC*NPH];
__device__ float g_hhb [(size_t)NB*NC*NPH];
__device__ float g_tA  [(size_t)NB*NC*NPH];
__device__ float g_tB  [(size_t)NB*NC*NPH];
__device__ float g_qlh [(size_t)NB*NC*NPH];
__device__ float g_qhl [(size_t)NB*NC*NPH];
__device__ float g_qhh [(size_t)NB*NC*NPH];
__device__ float g_cat [(size_t)NB*2*NC*NPH];
__device__ float g_mask[(size_t)NB*5*NC*NPH];   // 21M elems
__device__ float g_qll [(size_t)NB*NC*NPH];
__device__ float g_ao  [(size_t)NB*NC*NPF];
__device__ float g_att [NB*NHEAD*CPH*CPH];      // 4096
__device__ float g_inv [2*NB*NC];               // 512 (q norms, then k norms)

__device__ __forceinline__ float sigmoidf(float x) { return 1.f/(1.f+expf(-x)); }

// ---------------- generic 1x1 conv as tiled GEMM ----------------
// out[b][o][p] = epilogue( sum_c w[o*Cin+c]*x[b][c][p] + bias[o] )
// mode 0: plain; 1: sigmoid; 2: res + val*mask (res/mask indexed [b][o][p])
__global__ void conv1x1_kernel(const float* __restrict__ x, const float* __restrict__ w,
    const float* __restrict__ bias, float* __restrict__ out,
    const float* __restrict__ res, const float* __restrict__ mask,
    int Cin, int Np,
    long long inBS, long long outBS, long long resBS, long long maskBS, int mode)
{
    const int b  = blockIdx.z;
    const int o0 = blockIdx.y * 64;
    const int p0 = blockIdx.x * 64;
    const float* xb = x + (long long)b*inBS + p0;
    float* ob = out + (long long)b*outBS + p0;

    __shared__ float sW[8][64];
    __shared__ float sX[8][64];

    const int tid = threadIdx.x;         // 256 threads
    const int tx = tid & 15, ty = tid >> 4;

    float acc[4][4];
#pragma unroll
    for (int i = 0; i < 4; i++)
#pragma unroll
        for (int j = 0; j < 4; j++) acc[i][j] = 0.f;

    for (int k0 = 0; k0 < Cin; k0 += 8) {
        int i = tid;
#pragma unroll
        for (int r = 0; r < 2; r++, i += 256) {
            int o  = i >> 3, kk = i & 7;
            sW[kk][o] = w[(long long)(o0 + o)*Cin + k0 + kk];
            int kk2 = i >> 6, p = i & 63;
            sX[kk2][p] = xb[(long long)(k0 + kk2)*Np + p];
        }
        __syncthreads();
#pragma unroll
        for (int kk = 0; kk < 8; kk++) {
            float4 av = *reinterpret_cast<const float4*>(&sW[kk][ty*4]);
            float4 bv = *reinterpret_cast<const float4*>(&sX[kk][tx*4]);
            float a0[4] = {av.x, av.y, av.z, av.w};
            float b0[4] = {bv.x, bv.y, bv.z, bv.w};
#pragma unroll
            for (int ii = 0; ii < 4; ii++)
#pragma unroll
                for (int jj = 0; jj < 4; jj++) acc[ii][jj] += a0[ii]*b0[jj];
        }
        __syncthreads();
    }

    const float* rb = (mode == 2) ? res  + (long long)b*resBS  + p0 : nullptr;
    const float* mb = (mode == 2) ? mask + (long long)b*maskBS + p0 : nullptr;

#pragma unroll
    for (int ii = 0; ii < 4; ii++) {
        int oc = o0 + ty*4 + ii;
        float bi = bias[oc];
#pragma unroll
        for (int jj = 0; jj < 4; jj++) {
            int pl = tx*4 + jj;
            float v = acc[ii][jj] + bi;
            if (mode == 1) {
                v = sigmoidf(v);
            } else if (mode == 2) {
                v = rb[(long long)oc*Np + pl] + v * mb[(long long)oc*Np + pl];
            }
            ob[(long long)oc*Np + pl] = v;
        }
    }
}

// ---------------- depthwise conv (plain or gated: dw0 * sigmoid(dw1)) ----------------
__global__ void dw_kernel(const float* __restrict__ in, const float* __restrict__ w0,
    const float* __restrict__ w1, float* __restrict__ out,
    int C, int Hi, int Wi, int kh, int kw, long long inBS, long long outBS)
{
    const int bc = blockIdx.z;
    const int b = bc / C, c = bc - b*C;
    const int ph = kh >> 1, pw = kw >> 1;
    const float* ip = in  + (long long)b*inBS  + (long long)c*Hi*Wi;
    float*       op = out + (long long)b*outBS + (long long)c*Hi*Wi;
    const int x0 = blockIdx.x*32, y0 = blockIdx.y*8;

    __shared__ float tile[12*36]; // max (8+4)x(32+4)
    const int tw = 32 + 2*pw, th = 8 + 2*ph;
    const int tid = threadIdx.y*32 + threadIdx.x;

    for (int i = tid; i < th*tw; i += 256) {
        int tyy = i / tw, txx = i - tyy*tw;
        int gy = y0 - ph + tyy, gx = x0 - pw + txx;
        float v = 0.f;
        if (gy >= 0 && gy < Hi && gx >= 0 && gx < Wi)
            v = ip[(long long)gy*Wi + gx];
        tile[i] = v;
    }
    __syncthreads();

    const int tx = threadIdx.x, ty = threadIdx.y;
    const float* wc0 = w0 + (long long)c*kh*kw;
    float s0 = 0.f;
    if (w1) {
        const float* wc1 = w1 + (long long)c*kh*kw;
        float s1 = 0.f;
        for (int ky = 0; ky < kh; ky++)
            for (int kx = 0; kx < kw; kx++) {
                float t = tile[(ty+ky)*tw + tx+kx];
                s0 += wc0[ky*kw+kx]*t;
                s1 += wc1[ky*kw+kx]*t;
            }
        s0 = s0 * sigmoidf(s1);
    } else {
        for (int ky = 0; ky < kh; ky++)
            for (int kx = 0; kx < kw; kx++)
                s0 += wc0[ky*kw+kx]*tile[(ty+ky)*tw + tx+kx];
    }
    op[(long long)(y0+ty)*Wi + x0+tx] = s0;
}

// ---------------- fused: depthwise 3x3 on q slice + Haar DWT -> 4 subbands ----------------
// Full-res 32x8 tile is 2x2 aligned, so the DWT of the tile is self-contained.
__global__ void dwq_dwt_kernel(const float* __restrict__ in, const float* __restrict__ w0,
                               long long inBS)
{
    const int bc = blockIdx.z;            // b*NC + c
    const int b = bc >> 7, c = bc & 127;
    const float* ip = in + (long long)b*inBS + (long long)c*NPF;
    const int x0 = blockIdx.x*32, y0 = blockIdx.y*8;

    __shared__ float tile[10*34];
    __shared__ float sOut[8][32];
    const int tw = 34, th = 10;
    const int tid = threadIdx.y*32 + threadIdx.x;

    for (int i = tid; i < th*tw; i += 256) {
        int tyy = i / tw, txx = i - tyy*tw;
        int gy = y0 - 1 + tyy, gx = x0 - 1 + txx;
        float v = 0.f;
        if (gy >= 0 && gy < HF && gx >= 0 && gx < WF)
            v = ip[(long long)gy*WF + gx];
        tile[i] = v;
    }
    __syncthreads();

    const int tx = threadIdx.x, ty = threadIdx.y;
    const float* wc0 = w0 + c*9;
    float s0 = 0.f;
#pragma unroll
    for (int ky = 0; ky < 3; ky++)
#pragma unroll
        for (int kx = 0; kx < 3; kx++)
            s0 += wc0[ky*3+kx]*tile[(ty+ky)*tw + tx+kx];
    sOut[ty][tx] = s0;
    __syncthreads();

    // DWT: 64 2x2 blocks in this tile -> threads 0..63
    if (tid < 64) {
        int by = tid >> 4, bx = tid & 15;            // by in [0,4), bx in [0,16)
        float a  = sOut[2*by  ][2*bx  ];
        float b_ = sOut[2*by  ][2*bx+1];
        float c_ = sOut[2*by+1][2*bx  ];
        float d_ = sOut[2*by+1][2*bx+1];
        long long o = (long long)bc*NPH + (long long)(y0/2 + by)*WHALF + (x0/2 + bx);
        g_ll [o] = (a + b_ + c_ + d_)*0.5f;
        g_lhb[o] = (a + b_ - c_ - d_)*0.5f;
        g_hlb[o] = (a - b_ + c_ - d_)*0.5f;
        g_hhb[o] = (a - b_ - c_ + d_)*0.5f;
    }
}

// ---------------- IDWT with fused subband masks -> g_qbuf (full res) ----------------
__global__ void idwt_kernel(const float* __restrict__ masks)
{
    long long idx = (long long)blockIdx.x*256 + threadIdx.x;
    if (idx >= (long long)NB*NC*NPH) return;
    int p = (int)(idx & (NPH-1));
    long long bc = idx >> 14;
    long long b = bc >> 7;        // /128
    int c = (int)(bc & 127);
    const float* mbase = masks + b*(5LL*NC*NPH) + p;
    float mlh = mbase[(long long)(1*NC + c)*NPH];
    float mhl = mbase[(long long)(2*NC + c)*NPH];
    float mhh = mbase[(long long)(3*NC + c)*NPH];
    float ll = g_qll[idx];
    float lh = g_qlh[idx]*mlh;
    float hl = g_qhl[idx]*mhl;
    float hh = g_qhh[idx]*mhh;
    float a  = (ll + lh + hl + hh)*0.5f;
    float bb = (ll + lh - hl - hh)*0.5f;
    float cc = (ll - lh + hl - hh)*0.5f;
    float dd = (ll - lh - hl + hh)*0.5f;
    int y = p >> 7, x = p & 127;
    float* op = g_qbuf + bc*NPF;
    op[(long long)(2*y)*WF + 2*x]     = a;
    op[(long long)(2*y)*WF + 2*x+1]   = bb;
    op[(long long)(2*y+1)*WF + 2*x]   = cc;
    op[(long long)(2*y+1)*WF + 2*x+1] = dd;
}

// ---------------- per-channel inverse L2 norms of q and k; also zero g_att ----------------
__global__ void norm_kernel()
{
    if (blockIdx.x == 0) {
        for (int i = threadIdx.x; i < NB*NHEAD*CPH*CPH; i += 256) g_att[i] = 0.f;
    }
    int row = blockIdx.x;                       // 0..255 -> q rows, 256..511 -> k rows
    const float* base = (row < 256) ? g_qbuf : g_kbuf;
    const float* p = base + (long long)(row & 255)*NPF;
    float s = 0.f;
    for (int i = threadIdx.x; i < NPF; i += 256) { float v = p[i]; s += v*v; }
    __shared__ float red[256];
    red[threadIdx.x] = s;
    __syncthreads();
    for (int off = 128; off > 0; off >>= 1) {
        if (threadIdx.x < off) red[threadIdx.x] += red[threadIdx.x + off];
        __syncthreads();
    }
    if (threadIdx.x == 0) g_inv[row] = 1.f / fmaxf(sqrtf(red[0]), 1e-12f);
}

// ---------------- Gram: att[bh][i][j] += sum_n q[i][n]*k[j][n] over a slice ----------------
__global__ void gram_kernel()
{
    const int bh = blockIdx.y;
    const int b = bh >> 3, h = bh & 7;
    const float* qb = g_qbuf + ((long long)b*NC + h*CPH)*NPF;
    const float* kb = g_kbuf + ((long long)b*NC + h*CPH)*NPF;
    __shared__ float sq[16][129];
    __shared__ float sk[16][129];
    const int tid = threadIdx.x;
    const int i = tid >> 4, j = tid & 15;
    const int n0 = blockIdx.x * (NPF/64);       // 1024-wide slice
    float acc = 0.f;
    for (int ch = 0; ch < NPF/64; ch += 128) {
        for (int t = tid; t < 16*128; t += 256) {
            int d = t >> 7, nn = t & 127;
            sq[d][nn] = qb[(long long)d*NPF + n0 + ch + nn];
            sk[d][nn] = kb[(long long)d*NPF + n0 + ch + nn];
        }
        __syncthreads();
#pragma unroll 8
        for (int nn = 0; nn < 128; nn++) acc += sq[i][nn]*sk[j][nn];
        __syncthreads();
    }
    atomicAdd(&g_att[bh*256 + i*16 + j], acc);
}

// ---------------- scale by inv-norms & temperature, softmax over j ----------------
__global__ void softmax_kernel(const float* __restrict__ temp)
{
    const int t = threadIdx.x;                  // 256 = one thread per (bh, row i)
    const int bh = t >> 4, i = t & 15;
    const int b = bh >> 3, h = bh & 7;
    const float iq = g_inv[b*NC + h*CPH + i];
    const float tp = temp[h];
    float s[16];
    float mx = -1e30f;
#pragma unroll
    for (int j = 0; j < 16; j++) {
        float ik = g_inv[256 + b*NC + h*CPH + j];
        float v = g_att[bh*256 + i*16 + j] * iq * ik * tp;
        s[j] = v;
        mx = fmaxf(mx, v);
    }
    float sum = 0.f;
#pragma unroll
    for (int j = 0; j < 16; j++) { s[j] = expf(s[j] - mx); sum += s[j]; }
    float inv = 1.f / sum;
#pragma unroll
    for (int j = 0; j < 16; j++) g_att[bh*256 + i*16 + j] = s[j]*inv;
}

// ---------------- out[i][n] = sum_j att[i][j] * v[j][n] ----------------
__global__ void av_kernel()
{
    const int bh = blockIdx.y;
    const int b = bh >> 3, h = bh & 7;
    __shared__ float sa[256];
    sa[threadIdx.x] = g_att[bh*256 + threadIdx.x];
    __syncthreads();
    const long long n = (long long)blockIdx.x*256 + threadIdx.x;
    const float* vb = g_vbuf + ((long long)b*NC + h*CPH)*NPF + n;
    float*       ob = g_ao   + ((long long)b*NC + h*CPH)*NPF + n;
    float acc[16];
#pragma unroll
    for (int i = 0; i < 16; i++) acc[i] = 0.f;
#pragma unroll
    for (int j = 0; j < 16; j++) {
        float vj = vb[(long long)j*NPF];
#pragma unroll
        for (int i = 0; i < 16; i++) acc[i] += sa[i*16 + j]*vj;
    }
#pragma unroll
    for (int i = 0; i < 16; i++) ob[(long long)i*NPF] = acc[i];
}

// ---------------- host launch ----------------
extern "C" void kernel_launch(void* const* d_in, const int* in_sizes, int n_in,
                              void* d_out, int out_size)
{
    const float* x       = (const float*)d_in[0];
    const float* prior   = (const float*)d_in[1];
    const float* w_lin   = (const float*)d_in[2];
    const float* b_lin   = (const float*)d_in[3];
    const float* w_qd    = (const float*)d_in[4];
    const float* w_kd    = (const float*)d_in[5];
    const float* w_vd    = (const float*)d_in[6];
    const float* g_wllr  = (const float*)d_in[7];
    const float* g_wllh  = (const float*)d_in[8];
    const float* g_wlh   = (const float*)d_in[9];
    const float* g_whl   = (const float*)d_in[10];
    const float* g_whh   = (const float*)d_in[11];
    const float* w_prior = (const float*)d_in[12];
    const float* b_prior = (const float*)d_in[13];
    const float* w_pw1   = (const float*)d_in[14];
    const float* b_pw1   = (const float*)d_in[15];
    const float* w_pw2   = (const float*)d_in[16];
    const float* b_pw2   = (const float*)d_in[17];
    const float* w_cat   = (const float*)d_in[18];
    const float* b_cat   = (const float*)d_in[19];
    const float* temp    = (const float*)d_in[20];
    const float* w_out   = (const float*)d_in[21];
    const float* b_out   = (const float*)d_in[22];
    float* out = (float*)d_out;

    float *p_qkv, *p_q, *p_k, *p_v, *p_ll, *p_lh, *p_hl, *p_hh;
    float *p_tA, *p_tB, *p_qlh, *p_qhl, *p_qhh, *p_cat, *p_mask, *p_qll, *p_ao;
    cudaGetSymbolAddress((void**)&p_qkv,  g_qkv);
    cudaGetSymbolAddress((void**)&p_q,    g_qbuf);
    cudaGetSymbolAddress((void**)&p_k,    g_kbuf);
    cudaGetSymbolAddress((void**)&p_v,    g_vbuf);
    cudaGetSymbolAddress((void**)&p_ll,   g_ll);
    cudaGetSymbolAddress((void**)&p_lh,   g_lhb);
    cudaGetSymbolAddress((void**)&p_hl,   g_hlb);
    cudaGetSymbolAddress((void**)&p_hh,   g_hhb);
    cudaGetSymbolAddress((void**)&p_tA,   g_tA);
    cudaGetSymbolAddress((void**)&p_tB,   g_tB);
    cudaGetSymbolAddress((void**)&p_qlh,  g_qlh);
    cudaGetSymbolAddress((void**)&p_qhl,  g_qhl);
    cudaGetSymbolAddress((void**)&p_qhh,  g_qhh);
    cudaGetSymbolAddress((void**)&p_cat,  g_cat);
    cudaGetSymbolAddress((void**)&p_mask, g_mask);
    cudaGetSymbolAddress((void**)&p_qll,  g_qll);
    cudaGetSymbolAddress((void**)&p_ao,   g_ao);

    const dim3 dwb(32, 8);
    const dim3 dwgF(WF/32, HF/8, NB*NC);
    const dim3 dwgH(WHALF/32, HHALF/8, NB*NC);

    // 1) qkv = conv1x1(x): 128 -> 384 @ full res
    conv1x1_kernel<<<dim3(NPF/64, 384/64, NB), 256>>>(
        x, w_lin, b_lin, p_qkv, nullptr, nullptr,
        128, NPF, 128LL*NPF, 384LL*NPF, 0, 0, 0);

    // 2) masks = sigmoid(conv1x1(prior)): 128 -> 640 @ half res
    conv1x1_kernel<<<dim3(NPH/64, 640/64, NB), 256>>>(
        prior, w_prior, b_prior, p_mask, nullptr, nullptr,
        128, NPH, 128LL*NPH, 640LL*NPH, 0, 0, 1);

    // 3) fused depthwise 3x3 + DWT on q; plain depthwise on k, v
    dwq_dwt_kernel<<<dwgF, dwb>>>(p_qkv, w_qd, 384LL*NPF);
    dw_kernel<<<dwgF, dwb>>>(p_qkv + 128LL*NPF, w_kd, nullptr, p_k, NC, HF, WF, 3, 3, 384LL*NPF, 128LL*NPF);
    dw_kernel<<<dwgF, dwb>>>(p_qkv + 256LL*NPF, w_vd, nullptr, p_v, NC, HF, WF, 3, 3, 384LL*NPF, 128LL*NPF);

    // 4) gated chain llr (2 steps, 3x3), then residual pw1*m_ll -> cat channels [0,128)
    dw_kernel<<<dwgH, dwb>>>(p_ll, g_wllr + 0*NC*9, g_wllr + 1*NC*9, p_tA, NC, HHALF, WHALF, 3, 3, 128LL*NPH, 128LL*NPH);
    dw_kernel<<<dwgH, dwb>>>(p_tA, g_wllr + 2*NC*9, g_wllr + 3*NC*9, p_tB, NC, HHALF, WHALF, 3, 3, 128LL*NPH, 128LL*NPH);
    conv1x1_kernel<<<dim3(NPH/64, 2, NB), 256>>>(
        p_tB, w_pw1, b_pw1, p_cat, p_tB, p_mask,
        128, NPH, 128LL*NPH, 256LL*NPH, 128LL*NPH, 640LL*NPH, 2);

    // 5) gated chain llh (2 steps, 3x3), then residual pw2*m_hp -> cat channels [128,256)
    dw_kernel<<<dwgH, dwb>>>(p_ll, g_wllh + 0*NC*9, g_wllh + 1*NC*9, p_tA, NC, HHALF, WHALF, 3, 3, 128LL*NPH, 128LL*NPH);
    dw_kernel<<<dwgH, dwb>>>(p_tA, g_wllh + 2*NC*9, g_wllh + 3*NC*9, p_tB, NC, HHALF, WHALF, 3, 3, 128LL*NPH, 128LL*NPH);
    conv1x1_kernel<<<dim3(NPH/64, 2, NB), 256>>>(
        p_tB, w_pw2, b_pw2, p_cat + 128LL*NPH, p_tB, p_mask + 512LL*NPH,
        128, NPH, 128LL*NPH, 256LL*NPH, 128LL*NPH, 640LL*NPH, 2);

    // 6) single-step gates on LH (3x5), HL (5x3), HH (3x3)
    dw_kernel<<<dwgH, dwb>>>(p_lh, g_wlh, g_wlh + NC*15, p_qlh, NC, HHALF, WHALF, 3, 5, 128LL*NPH, 128LL*NPH);
    dw_kernel<<<dwgH, dwb>>>(p_hl, g_whl, g_whl + NC*15, p_qhl, NC, HHALF, WHALF, 5, 3, 128LL*NPH, 128LL*NPH);
    dw_kernel<<<dwgH, dwb>>>(p_hh, g_whh, g_whh + NC*9,  p_qhh, NC, HHALF, WHALF, 3, 3, 128LL*NPH, 128LL*NPH);

    // 7) q_ll = conv1x1(cat): 256 -> 128 @ half res
    conv1x1_kernel<<<dim3(NPH/64, 2, NB), 256>>>(
        p_cat, w_cat, b_cat, p_qll, nullptr, nullptr,
        256, NPH, 256LL*NPH, 128LL*NPH, 0, 0, 0);

    // 8) IDWT (fused subband masks) -> reconstructed q into g_qbuf
    idwt_kernel<<<(NB*NC*NPH)/256, 256>>>(p_mask);

    // 9) attention
    norm_kernel<<<512, 256>>>();
    gram_kernel<<<dim3(64, 16), 256>>>();
    softmax_kernel<<<1, 256>>>(temp);
    av_kernel<<<dim3(NPF/256, 16), 256>>>();

    // 10) final conv1x1: 128 -> 128 @ full res, writes d_out
    conv1x1_kernel<<<dim3(NPF/64, 2, NB), 256>>>(
        p_ao, w_out, b_out, out, nullptr, nullptr,
        128, NPF, 128LL*NPF, 128LL*NPF, 0, 0, 0);

    // 11) second output: prior passthrough
    long long first = (long long)NB*NC*NPF;
    long long second = (long long)NB*NC*NPH;
    if ((long long)out_size >= first + second) {
        cudaMemcpyAsync(out + first, prior, sizeof(float)*(size_t)second,
                        cudaMemcpyDeviceToDevice);
    }
}

// round 16
// speedup vs baseline: 1.8745x; 1.8745x over previous
#include <cuda_runtime.h>
#include <cstdint>

// Problem constants
#define NB 2
#define NC 128
#define HF 256
#define WF 256
#define NPF (HF*WF)          // 65536 pixels full res
#define HHALF 128
#define WHALF 128
#define NPH (HHALF*WHALF)    // 16384 pixels half res
#define NHEAD 8
#define CPH 16               // channels per head

// ---------------- scratch (static device globals; no allocations) ----------------
__device__ float g_qkv [(size_t)NB*3*NC*NPF];
__device__ float g_qbuf[(size_t)NB*NC*NPF];     // reconstructed q (after IDWT)
__device__ float g_kbuf[(size_t)NB*NC*NPF];
__device__ float g_vbuf[(size_t)NB*NC*NPF];
__device__ float g_ll  [(size_t)NB*NC*NPH];
__device__ float g_lhb [(size_t)NB*NC*NPH];
__device__ float g_hlb [(size_t)NB*NC*NPH];
__device__ float g_hhb [(size_t)NB*NC*NPH];
__device__ float g_tA  [(size_t)NB*NC*NPH];
__device__ float g_tB  [(size_t)NB*NC*NPH];
__device__ float g_qlh [(size_t)NB*NC*NPH];
__device__ float g_qhl [(size_t)NB*NC*NPH];
__device__ float g_qhh [(size_t)NB*NC*NPH];
__device__ float g_cat [(size_t)NB*2*NC*NPH];
__device__ float g_mask[(size_t)NB*5*NC*NPH];
__device__ float g_qll [(size_t)NB*NC*NPH];
__device__ float g_att [NB*NHEAD*CPH*CPH];      // 4096
__device__ float g_nrm [2*NB*NC];               // 512 raw sum-of-squares (q rows, then k rows)
__device__ float g_weff[NB*NC*NC];              // per-batch composed output weights

__device__ __forceinline__ float sigmoidf(float x) { return 1.f/(1.f+expf(-x)); }

// ---------------- 1x1 conv as 128x128-tile SGEMM, 8x8 per thread, double-buffered ----------------
// out[b][o][p] = epilogue( sum_c w[b*wBS + o*Cin+c]*x[b][c][p] + bias[o] )
// mode 0: plain; 1: sigmoid; 2: res + val*mask
__global__ void __launch_bounds__(256) conv1x1_kernel(
    const float* __restrict__ x, const float* __restrict__ w,
    const float* __restrict__ bias, float* __restrict__ out,
    const float* __restrict__ res, const float* __restrict__ mask,
    int Cin, int Np,
    long long inBS, long long outBS, long long resBS, long long maskBS,
    long long wBS, int mode)
{
    const int b  = blockIdx.z;
    const int o0 = blockIdx.y * 128;
    const int p0 = blockIdx.x * 128;
    const float* xb = x + (long long)b*inBS;
    const float* wb = w + (long long)b*wBS;

    __shared__ float sA[2][8][128];
    __shared__ float sB[2][8][128];

    const int tid = threadIdx.x;
    // A (weights) loader: 128 rows x 8 k, each thread one float4 along K
    const int am = tid >> 1;
    const int ak = (tid & 1) * 4;
    // B (activations) loader: 8 k rows x 128 n, each thread one float4 along N
    const int bk = tid >> 5;
    const int bn = (tid & 31) * 4;
    const int nsteps = Cin >> 3;

    float4 ra = *reinterpret_cast<const float4*>(&wb[(long long)(o0+am)*Cin + ak]);
    float4 rb = *reinterpret_cast<const float4*>(&xb[(long long)bk*Np + p0 + bn]);
    sA[0][ak+0][am] = ra.x; sA[0][ak+1][am] = ra.y;
    sA[0][ak+2][am] = ra.z; sA[0][ak+3][am] = ra.w;
    *reinterpret_cast<float4*>(&sB[0][bk][bn]) = rb;
    __syncthreads();

    const int tx = (tid & 15) * 8;   // n offset
    const int ty = (tid >> 4) * 8;   // m offset
    float acc[8][8] = {};

    for (int s = 0; s < nsteps; s++) {
        const int cur = s & 1;
        if (s + 1 < nsteps) {
            const int k0 = (s + 1) * 8;
            ra = *reinterpret_cast<const float4*>(&wb[(long long)(o0+am)*Cin + k0 + ak]);
            rb = *reinterpret_cast<const float4*>(&xb[(long long)(k0+bk)*Np + p0 + bn]);
        }
#pragma unroll
        for (int kk = 0; kk < 8; kk++) {
            float a[8], bb[8];
            *reinterpret_cast<float4*>(&a[0])  = *reinterpret_cast<float4*>(&sA[cur][kk][ty]);
            *reinterpret_cast<float4*>(&a[4])  = *reinterpret_cast<float4*>(&sA[cur][kk][ty+4]);
            *reinterpret_cast<float4*>(&bb[0]) = *reinterpret_cast<float4*>(&sB[cur][kk][tx]);
            *reinterpret_cast<float4*>(&bb[4]) = *reinterpret_cast<float4*>(&sB[cur][kk][tx+4]);
#pragma unroll
            for (int i = 0; i < 8; i++)
#pragma unroll
                for (int j = 0; j < 8; j++) acc[i][j] += a[i]*bb[j];
        }
        if (s + 1 < nsteps) {
            const int nxt = cur ^ 1;
            sA[nxt][ak+0][am] = ra.x; sA[nxt][ak+1][am] = ra.y;
            sA[nxt][ak+2][am] = ra.z; sA[nxt][ak+3][am] = ra.w;
            *reinterpret_cast<float4*>(&sB[nxt][bk][bn]) = rb;
        }
        __syncthreads();
    }

    float* ob = out + (long long)b*outBS + p0;
    const float* rbp = (mode == 2) ? res  + (long long)b*resBS  + p0 : nullptr;
    const float* mbp = (mode == 2) ? mask + (long long)b*maskBS + p0 : nullptr;

#pragma unroll
    for (int i = 0; i < 8; i++) {
        const int oc = o0 + ty + i;
        const float bi = bias[oc];
        float v[8];
#pragma unroll
        for (int j = 0; j < 8; j++) v[j] = acc[i][j] + bi;
        if (mode == 1) {
#pragma unroll
            for (int j = 0; j < 8; j++) v[j] = sigmoidf(v[j]);
        } else if (mode == 2) {
#pragma unroll
            for (int j = 0; j < 8; j++)
                v[j] = rbp[(long long)oc*Np + tx + j] + v[j]*mbp[(long long)oc*Np + tx + j];
        }
        *reinterpret_cast<float4*>(&ob[(long long)oc*Np + tx])     = make_float4(v[0],v[1],v[2],v[3]);
        *reinterpret_cast<float4*>(&ob[(long long)oc*Np + tx + 4]) = make_float4(v[4],v[5],v[6],v[7]);
    }
}

// ---------------- templated depthwise: 64x16 tile, 4 px/thread, unrolled ----------------
template<int KH, int KW, bool GATED>
__global__ void __launch_bounds__(256) dwT_kernel(
    const float* __restrict__ in, const float* __restrict__ w0,
    const float* __restrict__ w1, float* __restrict__ out,
    int Hi, int Wi, long long inBS, long long outBS)
{
    constexpr int PH = KH/2, PW = KW/2;
    constexpr int TW = 64 + 2*PW;
    constexpr int TH = 16 + 2*PH;
    const int bc = blockIdx.z;
    const int b = bc >> 7, c = bc & 127;
    const float* ip = in  + (long long)b*inBS  + (long long)c*Hi*Wi;
    float*       op = out + (long long)b*outBS + (long long)c*Hi*Wi;
    const int x0 = blockIdx.x*64, y0 = blockIdx.y*16;

    __shared__ float tile[TH*TW];
    const int tid = threadIdx.y*16 + threadIdx.x;

    for (int i = tid; i < TH*TW; i += 256) {
        const int tyy = i / TW, txx = i - tyy*TW;
        const int gy = y0 - PH + tyy, gx = x0 - PW + txx;
        float v = 0.f;
        if (gy >= 0 && gy < Hi && gx >= 0 && gx < Wi) v = ip[gy*Wi + gx];
        tile[i] = v;
    }

    float W0[KH*KW], W1[GATED ? KH*KW : 1];
#pragma unroll
    for (int i = 0; i < KH*KW; i++) W0[i] = w0[c*KH*KW + i];
    if (GATED) {
#pragma unroll
        for (int i = 0; i < KH*KW; i++) W1[i] = w1[c*KH*KW + i];
    }
    __syncthreads();

    const int tx = threadIdx.x * 4, ty = threadIdx.y;
    float s0[4] = {0,0,0,0}, s1[4] = {0,0,0,0};
#pragma unroll
    for (int ky = 0; ky < KH; ky++) {
        float row[KW+3];
#pragma unroll
        for (int i = 0; i < KW+3; i++) row[i] = tile[(ty+ky)*TW + tx + i];
#pragma unroll
        for (int kx = 0; kx < KW; kx++) {
            const float wa = W0[ky*KW+kx];
            const float wb = GATED ? W1[ky*KW+kx] : 0.f;
#pragma unroll
            for (int j = 0; j < 4; j++) {
                s0[j] += wa*row[kx+j];
                if (GATED) s1[j] += wb*row[kx+j];
            }
        }
    }
    float4 r;
    if (GATED) {
        r.x = s0[0]*sigmoidf(s1[0]); r.y = s0[1]*sigmoidf(s1[1]);
        r.z = s0[2]*sigmoidf(s1[2]); r.w = s0[3]*sigmoidf(s1[3]);
    } else {
        r.x = s0[0]; r.y = s0[1]; r.z = s0[2]; r.w = s0[3];
    }
    *reinterpret_cast<float4*>(&op[(long long)(y0+ty)*Wi + x0 + tx]) = r;
}

// ---------------- fused: depthwise 3x3 on q slice + Haar DWT -> 4 subbands ----------------
__global__ void __launch_bounds__(256) dwq_dwt_kernel(
    const float* __restrict__ in, const float* __restrict__ w0, long long inBS)
{
    constexpr int TW = 66, TH = 18;
    const int bc = blockIdx.z;
    const int b = bc >> 7, c = bc & 127;
    const float* ip = in + (long long)b*inBS + (long long)c*NPF;
    const int x0 = blockIdx.x*64, y0 = blockIdx.y*16;

    __shared__ float tile[TH*TW];
    __shared__ float sOut[16][64];
    const int tid = threadIdx.y*16 + threadIdx.x;

    for (int i = tid; i < TH*TW; i += 256) {
        const int tyy = i / TW, txx = i - tyy*TW;
        const int gy = y0 - 1 + tyy, gx = x0 - 1 + txx;
        float v = 0.f;
        if (gy >= 0 && gy < HF && gx >= 0 && gx < WF) v = ip[gy*WF + gx];
        tile[i] = v;
    }
    float W0[9];
#pragma unroll
    for (int i = 0; i < 9; i++) W0[i] = w0[c*9 + i];
    __syncthreads();

    const int tx = threadIdx.x * 4, ty = threadIdx.y;
    float s0[4] = {0,0,0,0};
#pragma unroll
    for (int ky = 0; ky < 3; ky++) {
        float row[6];
#pragma unroll
        for (int i = 0; i < 6; i++) row[i] = tile[(ty+ky)*TW + tx + i];
#pragma unroll
        for (int kx = 0; kx < 3; kx++) {
            const float wa = W0[ky*3+kx];
#pragma unroll
            for (int j = 0; j < 4; j++) s0[j] += wa*row[kx+j];
        }
    }
    *reinterpret_cast<float4*>(&sOut[ty][tx]) = make_float4(s0[0],s0[1],s0[2],s0[3]);
    __syncthreads();

    // 2x2 Haar on the 64x16 tile -> 32x8 half-res region; 256 threads cover it
    const int by = tid >> 5, bx = tid & 31;
    const float a  = sOut[2*by  ][2*bx  ];
    const float b_ = sOut[2*by  ][2*bx+1];
    const float c_ = sOut[2*by+1][2*bx  ];
    const float d_ = sOut[2*by+1][2*bx+1];
    const long long o = (long long)bc*NPH + (long long)(y0/2 + by)*WHALF + (x0/2 + bx);
    g_ll [o] = (a + b_ + c_ + d_)*0.5f;
    g_lhb[o] = (a + b_ - c_ - d_)*0.5f;
    g_hlb[o] = (a - b_ + c_ - d_)*0.5f;
    g_hhb[o] = (a - b_ - c_ + d_)*0.5f;
}

// ---------------- IDWT with fused subband masks -> g_qbuf (full res) ----------------
__global__ void idwt_kernel(const float* __restrict__ masks)
{
    long long idx = (long long)blockIdx.x*256 + threadIdx.x;
    if (idx >= (long long)NB*NC*NPH) return;
    int p = (int)(idx & (NPH-1));
    long long bc = idx >> 14;
    long long b = bc >> 7;
    int c = (int)(bc & 127);
    const float* mbase = masks + b*(5LL*NC*NPH) + p;
    float mlh = mbase[(long long)(1*NC + c)*NPH];
    float mhl = mbase[(long long)(2*NC + c)*NPH];
    float mhh = mbase[(long long)(3*NC + c)*NPH];
    float ll = g_qll[idx];
    float lh = g_qlh[idx]*mlh;
    float hl = g_qhl[idx]*mhl;
    float hh = g_qhh[idx]*mhh;
    float a  = (ll + lh + hl + hh)*0.5f;
    float bb = (ll + lh - hl - hh)*0.5f;
    float cc = (ll - lh + hl - hh)*0.5f;
    float dd = (ll - lh - hl + hh)*0.5f;
    int y = p >> 7, x = p & 127;
    float* op = g_qbuf + bc*NPF;
    *reinterpret_cast<float2*>(&op[(long long)(2*y)*WF + 2*x])   = make_float2(a, bb);
    *reinterpret_cast<float2*>(&op[(long long)(2*y+1)*WF + 2*x]) = make_float2(cc, dd);
}

// ---------------- zero the attention + norm accumulators (ALL entries, strided) ----------------
__global__ void init_acc_kernel()
{
    for (int i = threadIdx.x; i < NB*NHEAD*CPH*CPH; i += 256) g_att[i] = 0.f;
    for (int i = threadIdx.x; i < 2*NB*NC; i += 256) g_nrm[i] = 0.f;
}

// ---------------- Gram + fused norm partials ----------------
// att[bh][i][j] += sum_n q[i][n]*k[j][n] over a 1024-wide slice.
// Additionally: thread tid accumulates sum-of-squares of row (tid>>3) over
// nn segment [(tid&7)*16, +16) — rows 0..15 = q, 16..31 = k — into g_nrm.
// Row pad = 132 floats (multiple of 4) so float4 smem stores stay 16B-aligned.
__global__ void gram_kernel()
{
    const int bh = blockIdx.y;
    const int b = bh >> 3, h = bh & 7;
    const float* qb = g_qbuf + ((long long)b*NC + h*CPH)*NPF;
    const float* kb = g_kbuf + ((long long)b*NC + h*CPH)*NPF;
    __shared__ float sq[16][132];
    __shared__ float sk[16][132];
    const int tid = threadIdx.x;
    const int i = tid >> 4, j = tid & 15;
    const int nr = tid >> 3;                 // 0..31: q rows 0-15, k rows 16-31
    const int ns = (tid & 7) * 16;           // segment start within 128-chunk
    const int n0 = blockIdx.x * (NPF/64);    // 1024-wide slice
    float acc = 0.f;
    float nacc = 0.f;
    for (int ch = 0; ch < NPF/64; ch += 128) {
        // 16 rows x 128 cols, float4: 16*32 = 512 vec-loads across 256 threads
        for (int t = tid; t < 16*32; t += 256) {
            int d = t >> 5, nn = (t & 31) * 4;
            *reinterpret_cast<float4*>(&sq[d][nn]) =
                *reinterpret_cast<const float4*>(&qb[(long long)d*NPF + n0 + ch + nn]);
            *reinterpret_cast<float4*>(&sk[d][nn]) =
                *reinterpret_cast<const float4*>(&kb[(long long)d*NPF + n0 + ch + nn]);
        }
        __syncthreads();
#pragma unroll 8
        for (int nn = 0; nn < 128; nn++) acc += sq[i][nn]*sk[j][nn];
        // norm partial: 16 elements of this thread's (row, segment)
        const float* nrow = (nr < 16) ? &sq[nr][ns] : &sk[nr-16][ns];
#pragma unroll
        for (int nn = 0; nn < 16; nn++) { float v = nrow[nn]; nacc += v*v; }
        __syncthreads();
    }
    atomicAdd(&g_att[bh*256 + i*16 + j], acc);
    // g_nrm layout: [0,256) q rows (b*NC + ch), [256,512) k rows
    const int chan = h*CPH + (nr & 15);
    const int base = (nr < 16) ? 0 : 256;
    atomicAdd(&g_nrm[base + b*NC + chan], nacc);
}

// ---------------- scale by inv-norms & temperature, softmax over j ----------------
__global__ void softmax_kernel(const float* __restrict__ temp)
{
    const int t = threadIdx.x;
    const int bh = t >> 4, i = t & 15;
    const int b = bh >> 3, h = bh & 7;
    const float iq = 1.f / fmaxf(sqrtf(g_nrm[b*NC + h*CPH + i]), 1e-12f);
    const float tp = temp[h];
    float s[16];
    float mx = -1e30f;
#pragma unroll
    for (int j = 0; j < 16; j++) {
        float ik = 1.f / fmaxf(sqrtf(g_nrm[256 + b*NC + h*CPH + j]), 1e-12f);
        float v = g_att[bh*256 + i*16 + j] * iq * ik * tp;
        s[j] = v;
        mx = fmaxf(mx, v);
    }
    float sum = 0.f;
#pragma unroll
    for (int j = 0; j < 16; j++) { s[j] = expf(s[j] - mx); sum += s[j]; }
    float inv = 1.f / sum;
#pragma unroll
    for (int j = 0; j < 16; j++) g_att[bh*256 + i*16 + j] = s[j]*inv;
}

// ---------------- compose W_eff[b] = W_out * blockdiag(att_b) ----------------
// W_eff[b][o][d] = sum_i w_out[o][h*16+i] * att[b,h][i][j],  d = h*16+j
__global__ void weff_kernel(const float* __restrict__ w_out)
{
    const int idx = blockIdx.x*256 + threadIdx.x;   // [0, NB*NC*NC)
    const int b = idx >> 14;
    const int o = (idx >> 7) & 127;
    const int d = idx & 127;
    const int h = d >> 4, j = d & 15;
    const float* wrow = w_out + o*NC + h*CPH;
    const float* arow = g_att + (b*NHEAD + h)*256 + j;
    float s = 0.f;
#pragma unroll
    for (int i = 0; i < 16; i++) s += wrow[i] * arow[i*16];
    g_weff[idx] = s;
}

// ---------------- host launch ----------------
extern "C" void kernel_launch(void* const* d_in, const int* in_sizes, int n_in,
                              void* d_out, int out_size)
{
    const float* x       = (const float*)d_in[0];
    const float* prior   = (const float*)d_in[1];
    const float* w_lin   = (const float*)d_in[2];
    const float* b_lin   = (const float*)d_in[3];
    const float* w_qd    = (const float*)d_in[4];
    const float* w_kd    = (const float*)d_in[5];
    const float* w_vd    = (const float*)d_in[6];
    const float* g_wllr  = (const float*)d_in[7];
    const float* g_wllh  = (const float*)d_in[8];
    const float* g_wlh   = (const float*)d_in[9];
    const float* g_whl   = (const float*)d_in[10];
    const float* g_whh   = (const float*)d_in[11];
    const float* w_prior = (const float*)d_in[12];
    const float* b_prior = (const float*)d_in[13];
    const float* w_pw1   = (const float*)d_in[14];
    const float* b_pw1   = (const float*)d_in[15];
    const float* w_pw2   = (const float*)d_in[16];
    const float* b_pw2   = (const float*)d_in[17];
    const float* w_cat   = (const float*)d_in[18];
    const float* b_cat   = (const float*)d_in[19];
    const float* temp    = (const float*)d_in[20];
    const float* w_out   = (const float*)d_in[21];
    const float* b_out   = (const float*)d_in[22];
    float* out = (float*)d_out;

    float *p_qkv, *p_k, *p_v, *p_ll, *p_lh, *p_hl, *p_hh;
    float *p_tA, *p_tB, *p_qlh, *p_qhl, *p_qhh, *p_cat, *p_mask, *p_qll, *p_weff;
    cudaGetSymbolAddress((void**)&p_qkv,  g_qkv);
    cudaGetSymbolAddress((void**)&p_k,    g_kbuf);
    cudaGetSymbolAddress((void**)&p_v,    g_vbuf);
    cudaGetSymbolAddress((void**)&p_ll,   g_ll);
    cudaGetSymbolAddress((void**)&p_lh,   g_lhb);
    cudaGetSymbolAddress((void**)&p_hl,   g_hlb);
    cudaGetSymbolAddress((void**)&p_hh,   g_hhb);
    cudaGetSymbolAddress((void**)&p_tA,   g_tA);
    cudaGetSymbolAddress((void**)&p_tB,   g_tB);
    cudaGetSymbolAddress((void**)&p_qlh,  g_qlh);
    cudaGetSymbolAddress((void**)&p_qhl,  g_qhl);
    cudaGetSymbolAddress((void**)&p_qhh,  g_qhh);
    cudaGetSymbolAddress((void**)&p_cat,  g_cat);
    cudaGetSymbolAddress((void**)&p_mask, g_mask);
    cudaGetSymbolAddress((void**)&p_qll,  g_qll);
    cudaGetSymbolAddress((void**)&p_weff, g_weff);

    const dim3 dwb(16, 16);
    const dim3 dwgF(WF/64, HF/16, NB*NC);
    const dim3 dwgH(WHALF/64, HHALF/16, NB*NC);

    // 0) zero attention + norm accumulators
    init_acc_kernel<<<1, 256>>>();

    // 1) qkv = conv1x1(x): 128 -> 384 @ full res
    conv1x1_kernel<<<dim3(NPF/128, 3, NB), 256>>>(
        x, w_lin, b_lin, p_qkv, nullptr, nullptr,
        128, NPF, 128LL*NPF, 384LL*NPF, 0, 0, 0, 0);

    // 2) masks = sigmoid(conv1x1(prior)): 128 -> 640 @ half res
    conv1x1_kernel<<<dim3(NPH/128, 5, NB), 256>>>(
        prior, w_prior, b_prior, p_mask, nullptr, nullptr,
        128, NPH, 128LL*NPH, 640LL*NPH, 0, 0, 0, 1);

    // 3) fused depthwise 3x3 + DWT on q; plain depthwise on k, v
    dwq_dwt_kernel<<<dwgF, dwb>>>(p_qkv, w_qd, 384LL*NPF);
    dwT_kernel<3,3,false><<<dwgF, dwb>>>(p_qkv + 128LL*NPF, w_kd, nullptr, p_k, HF, WF, 384LL*NPF, 128LL*NPF);
    dwT_kernel<3,3,false><<<dwgF, dwb>>>(p_qkv + 256LL*NPF, w_vd, nullptr, p_v, HF, WF, 384LL*NPF, 128LL*NPF);

    // 4) gated chain llr (2 steps, 3x3), then residual pw1*m_ll -> cat channels [0,128)
    dwT_kernel<3,3,true><<<dwgH, dwb>>>(p_ll, g_wllr + 0*NC*9, g_wllr + 1*NC*9, p_tA, HHALF, WHALF, 128LL*NPH, 128LL*NPH);
    dwT_kernel<3,3,true><<<dwgH, dwb>>>(p_tA, g_wllr + 2*NC*9, g_wllr + 3*NC*9, p_tB, HHALF, WHALF, 128LL*NPH, 128LL*NPH);
    conv1x1_kernel<<<dim3(NPH/128, 1, NB), 256>>>(
        p_tB, w_pw1, b_pw1, p_cat, p_tB, p_mask,
        128, NPH, 128LL*NPH, 256LL*NPH, 128LL*NPH, 640LL*NPH, 0, 2);

    // 5) gated chain llh (2 steps, 3x3), then residual pw2*m_hp -> cat channels [128,256)
    dwT_kernel<3,3,true><<<dwgH, dwb>>>(p_ll, g_wllh + 0*NC*9, g_wllh + 1*NC*9, p_tA, HHALF, WHALF, 128LL*NPH, 128LL*NPH);
    dwT_kernel<3,3,true><<<dwgH, dwb>>>(p_tA, g_wllh + 2*NC*9, g_wllh + 3*NC*9, p_tB, HHALF, WHALF, 128LL*NPH, 128LL*NPH);
    conv1x1_kernel<<<dim3(NPH/128, 1, NB), 256>>>(
        p_tB, w_pw2, b_pw2, p_cat + 128LL*NPH, p_tB, p_mask + 512LL*NPH,
        128, NPH, 128LL*NPH, 256LL*NPH, 128LL*NPH, 640LL*NPH, 0, 2);

    // 6) single-step gates on LH (3x5), HL (5x3), HH (3x3)
    dwT_kernel<3,5,true><<<dwgH, dwb>>>(p_lh, g_wlh, g_wlh + NC*15, p_qlh, HHALF, WHALF, 128LL*NPH, 128LL*NPH);
    dwT_kernel<5,3,true><<<dwgH, dwb>>>(p_hl, g_whl, g_whl + NC*15, p_qhl, HHALF, WHALF, 128LL*NPH, 128LL*NPH);
    dwT_kernel<3,3,true><<<dwgH, dwb>>>(p_hh, g_whh, g_whh + NC*9,  p_qhh, HHALF, WHALF, 128LL*NPH, 128LL*NPH);

    // 7) q_ll = conv1x1(cat): 256 -> 128 @ half res
    conv1x1_kernel<<<dim3(NPH/128, 1, NB), 256>>>(
        p_cat, w_cat, b_cat, p_qll, nullptr, nullptr,
        256, NPH, 256LL*NPH, 128LL*NPH, 0, 0, 0, 0);

    // 8) IDWT (fused subband masks) -> reconstructed q into g_qbuf
    idwt_kernel<<<(NB*NC*NPH)/256, 256>>>(p_mask);

    // 9) attention: Gram + fused norms, softmax, compose W_eff = W_out * blockdiag(att)
    gram_kernel<<<dim3(64, 16), 256>>>();
    softmax_kernel<<<1, 256>>>(temp);
    weff_kernel<<<(NB*NC*NC)/256, 256>>>(w_out);

    // 10) out = conv1x1 with per-batch W_eff over V (AV einsum folded in), writes d_out
    conv1x1_kernel<<<dim3(NPF/128, 1, NB), 256>>>(
        p_v, p_weff, b_out, out, nullptr, nullptr,
        128, NPF, 128LL*NPF, 128LL*NPF, 0, 0, (long long)NC*NC, 0);

    // 11) second output: prior passthrough
    long long first = (long long)NB*NC*NPF;
    long long second = (long long)NB*NC*NPH;
    if ((long long)out_size >= first + second) {
        cudaMemcpyAsync(out + first, prior, sizeof(float)*(size_t)second,
                        cudaMemcpyDeviceToDevice);
    }
}